// round 3
// baseline (speedup 1.0000x reference)
#include <cuda_runtime.h>
#include <cuda_bf16.h>

#define H 40
#define T 256
#define BATCH 8192
#define EPB 32            // elements per block
#define THREADS 64        // 2 warps, 16 elements per warp, 4 per thread
#define NBLOCKS (BATCH / EPB)   // 256

typedef unsigned long long u64;

// ---- shared memory layout (float offsets) ----
#define OFF_WIH1 0                       // [k 40][c 3][g 4]      = 480
#define OFF_B1   480                     // [k 40][g 4]           = 160
#define OFF_B2   640                     // [k 40][g 4]           = 160
#define OFF_WHH1 800                     // [k 40][kk pitch41][g4]= 6560
#define OFF_WIH2 (800 + 6560)            // 7360
#define OFF_WHH2 (800 + 2*6560)          // 13920
#define OFF_H1   (800 + 3*6560)          // 20480 : [e 32][kk pitch41] x float2{h,h}
#define OFF_H2   (OFF_H1 + 2624)         // 23104
#define SMEM_FLOATS (OFF_H2 + 2624)      // 25728
#define SMEM_BYTES (SMEM_FLOATS * 4)     // 102912

__device__ __forceinline__ void fma2(u64 &d, u64 a, u64 b) {
    asm("fma.rn.f32x2 %0, %1, %2, %0;" : "+l"(d) : "l"(a), "l"(b));
}
__device__ __forceinline__ u64 pack2(float x, float y) {
    u64 r; asm("mov.b64 %0, {%1, %2};" : "=l"(r) : "f"(x), "f"(y)); return r;
}
__device__ __forceinline__ void unpack2(u64 v, float &x, float &y) {
    asm("mov.b64 {%0, %1}, %2;" : "=f"(x), "=f"(y) : "l"(v));
}
__device__ __forceinline__ float sigf(float x) {
    return __fdividef(1.0f, 1.0f + __expf(-x));
}
__device__ __forceinline__ float tanh_(float x) {
    float e = __expf(-2.0f * x);
    return __fdividef(1.0f - e, 1.0f + e);
}

__global__ __launch_bounds__(THREADS)
void lstm2_fused_kernel(const float* __restrict__ x,
                        const float* __restrict__ W_ih1,
                        const float* __restrict__ W_hh1,
                        const float* __restrict__ b1,
                        const float* __restrict__ W_ih2,
                        const float* __restrict__ W_hh2,
                        const float* __restrict__ b2,
                        const float* __restrict__ W_fc,
                        const float* __restrict__ b_fc,
                        float* __restrict__ out)
{
    extern __shared__ float sm[];
    const int tid = threadIdx.x;

    // ---- stage weights, gate-interleaved ----
    for (int idx = tid; idx < 160 * 3; idx += THREADS) {
        int row = idx / 3, c = idx % 3;
        int g = row / H, k = row % H;
        sm[OFF_WIH1 + (k * 3 + c) * 4 + g] = W_ih1[idx];
    }
    for (int idx = tid; idx < 160; idx += THREADS) {
        int g = idx / H, k = idx % H;
        sm[OFF_B1 + k * 4 + g] = b1[idx];
        sm[OFF_B2 + k * 4 + g] = b2[idx];
    }
    for (int idx = tid; idx < 160 * H; idx += THREADS) {
        int row = idx / H, kk = idx % H;
        int g = row / H, k = row % H;
        sm[OFF_WHH1 + (k * 41 + kk) * 4 + g] = W_hh1[idx];
        sm[OFF_WIH2 + (k * 41 + kk) * 4 + g] = W_ih2[idx];
        sm[OFF_WHH2 + (k * 41 + kk) * 4 + g] = W_hh2[idx];
    }
    for (int idx = tid; idx < 2 * 2624; idx += THREADS) {
        sm[OFF_H1 + idx] = 0.0f;   // covers H1 and H2 (contiguous)
    }
    __syncthreads();

    const int lane = tid & 31;
    const int warp = tid >> 5;
    const int j    = lane & 7;     // k-slice (owns k0..k0+4)
    const int sub  = lane >> 3;    // element subgroup within warp
    const int k0   = j * 5;

    int eb[4];
    long ge[4];
    const float* xb[4];
    #pragma unroll
    for (int b = 0; b < 4; b++) {
        eb[b] = warp * 16 + sub * 4 + b;
        ge[b] = (long)blockIdx.x * EPB + eb[b];
        xb[b] = x + ge[b] * (T * 3);
    }

    float c1[5][4], c2[5][4];
    #pragma unroll
    for (int k = 0; k < 5; k++)
        #pragma unroll
        for (int b = 0; b < 4; b++) { c1[k][b] = 0.0f; c2[k][b] = 0.0f; }

    u64 aA[5][4], aB[5][4];   // layer-1 gate accumulators (i,f) / (g,o)
    u64 gA[5][4], gB[5][4];   // layer-2 gate accumulators (persist B->C->A)
    float xv[4][3], xn[4][3];

    #pragma unroll
    for (int b = 0; b < 4; b++)
        #pragma unroll
        for (int c = 0; c < 3; c++)
            xv[b][c] = __ldg(xb[b] + c);

    // ---------------- phase bodies ----------------
    auto PREFETCH_X = [&](int t) {
        int tn = (t + 1 < T) ? (t + 1) : (T - 1);
        #pragma unroll
        for (int b = 0; b < 4; b++)
            #pragma unroll
            for (int c = 0; c < 3; c++)
                xn[b][c] = __ldg(xb[b] + tn * 3 + c);
    };

    auto L1_MATVEC = [&] {   // aA/aB = b1 + W_ih1*x(t) + W_hh1*h1(t-1)
        #pragma unroll
        for (int k = 0; k < 5; k++) {
            ulonglong2 bb = *(const ulonglong2*)(sm + OFF_B1 + (k0 + k) * 4);
            #pragma unroll
            for (int b = 0; b < 4; b++) { aA[k][b] = bb.x; aB[k][b] = bb.y; }
        }
        #pragma unroll
        for (int c = 0; c < 3; c++) {
            u64 xp[4];
            #pragma unroll
            for (int b = 0; b < 4; b++) xp[b] = pack2(xv[b][c], xv[b][c]);
            #pragma unroll
            for (int k = 0; k < 5; k++) {
                ulonglong2 w = *(const ulonglong2*)(sm + OFF_WIH1 + ((k0 + k) * 3 + c) * 4);
                #pragma unroll
                for (int b = 0; b < 4; b++) {
                    fma2(aA[k][b], w.x, xp[b]);
                    fma2(aB[k][b], w.y, xp[b]);
                }
            }
        }
        for (int kk0 = 0; kk0 < H; kk0 += 5) {
            #pragma unroll
            for (int u = 0; u < 5; u++) {
                int kk = kk0 + u;
                u64 hp[4];
                #pragma unroll
                for (int b = 0; b < 4; b++)
                    hp[b] = *(const u64*)(sm + OFF_H1 + (eb[b] * 41 + kk) * 2);
                #pragma unroll
                for (int k = 0; k < 5; k++) {
                    ulonglong2 w = *(const ulonglong2*)(sm + OFF_WHH1 + ((k0 + k) * 41 + kk) * 4);
                    #pragma unroll
                    for (int b = 0; b < 4; b++) {
                        fma2(aA[k][b], w.x, hp[b]);
                        fma2(aB[k][b], w.y, hp[b]);
                    }
                }
            }
        }
    };

    auto L1_ACT = [&] {      // consume aA/aB -> write h1(t)
        #pragma unroll
        for (int k = 0; k < 5; k++) {
            #pragma unroll
            for (int b = 0; b < 4; b++) {
                float gi, gf, gg, go;
                unpack2(aA[k][b], gi, gf);
                unpack2(aB[k][b], gg, go);
                gi = sigf(gi); gf = sigf(gf); gg = tanh_(gg); go = sigf(go);
                c1[k][b] = fmaf(gf, c1[k][b], gi * gg);
                float h = go * tanh_(c1[k][b]);
                *(u64*)(sm + OFF_H1 + (eb[b] * 41 + k0 + k) * 2) = pack2(h, h);
            }
        }
    };

    auto L2_HH2 = [&] {      // gA/gB = b2 + W_hh2*h2(t-1)
        #pragma unroll
        for (int k = 0; k < 5; k++) {
            ulonglong2 bb = *(const ulonglong2*)(sm + OFF_B2 + (k0 + k) * 4);
            #pragma unroll
            for (int b = 0; b < 4; b++) { gA[k][b] = bb.x; gB[k][b] = bb.y; }
        }
        for (int kk0 = 0; kk0 < H; kk0 += 5) {
            #pragma unroll
            for (int u = 0; u < 5; u++) {
                int kk = kk0 + u;
                u64 hp[4];
                #pragma unroll
                for (int b = 0; b < 4; b++)
                    hp[b] = *(const u64*)(sm + OFF_H2 + (eb[b] * 41 + kk) * 2);
                #pragma unroll
                for (int k = 0; k < 5; k++) {
                    ulonglong2 w = *(const ulonglong2*)(sm + OFF_WHH2 + ((k0 + k) * 41 + kk) * 4);
                    #pragma unroll
                    for (int b = 0; b < 4; b++) {
                        fma2(gA[k][b], w.x, hp[b]);
                        fma2(gB[k][b], w.y, hp[b]);
                    }
                }
            }
        }
    };

    auto L2_IH2 = [&] {      // gA/gB += W_ih2 * h1(t)
        for (int kk0 = 0; kk0 < H; kk0 += 5) {
            #pragma unroll
            for (int u = 0; u < 5; u++) {
                int kk = kk0 + u;
                u64 hp[4];
                #pragma unroll
                for (int b = 0; b < 4; b++)
                    hp[b] = *(const u64*)(sm + OFF_H1 + (eb[b] * 41 + kk) * 2);
                #pragma unroll
                for (int k = 0; k < 5; k++) {
                    ulonglong2 w = *(const ulonglong2*)(sm + OFF_WIH2 + ((k0 + k) * 41 + kk) * 4);
                    #pragma unroll
                    for (int b = 0; b < 4; b++) {
                        fma2(gA[k][b], w.x, hp[b]);
                        fma2(gB[k][b], w.y, hp[b]);
                    }
                }
            }
        }
    };

    auto L2_ACT = [&] {      // consume gA/gB -> write h2
        #pragma unroll
        for (int k = 0; k < 5; k++) {
            #pragma unroll
            for (int b = 0; b < 4; b++) {
                float gi, gf, gg, go;
                unpack2(gA[k][b], gi, gf);
                unpack2(gB[k][b], gg, go);
                gi = sigf(gi); gf = sigf(gf); gg = tanh_(gg); go = sigf(go);
                c2[k][b] = fmaf(gf, c2[k][b], gi * gg);
                float h = go * tanh_(c2[k][b]);
                *(u64*)(sm + OFF_H2 + (eb[b] * 41 + k0 + k) * 2) = pack2(h, h);
            }
        }
    };

    auto NEXT_X = [&] {
        #pragma unroll
        for (int b = 0; b < 4; b++) {
            xv[b][0] = xn[b][0]; xv[b][1] = xn[b][1]; xv[b][2] = xn[b][2];
        }
    };

    // ---------------- pipelined timeline ----------------
    // t = 0 (peeled: no L2_ACT yet)
    PREFETCH_X(0);
    L1_MATVEC();
    __syncwarp();
    L1_ACT();            // MUFU overlaps with L2_HH2 FMA (same BB)
    L2_HH2();
    __syncwarp();
    L2_IH2();
    NEXT_X();

    for (int t = 1; t < T; t++) {
        PREFETCH_X(t);
        L2_ACT();        // step t-1 activations, overlap with L1_MATVEC FMA
        L1_MATVEC();     // step t
        __syncwarp();
        L1_ACT();        // overlap with L2_HH2
        L2_HH2();
        __syncwarp();
        L2_IH2();
        NEXT_X();
    }
    L2_ACT();            // final h2(T-1)
    __syncwarp();

    // ---------------- FC epilogue ----------------
    if (j < 2) {
        float wfc[H];
        #pragma unroll 8
        for (int kk = 0; kk < H; kk++) wfc[kk] = W_fc[j * H + kk];
        float bias = b_fc[j];
        #pragma unroll
        for (int b = 0; b < 4; b++) {
            float acc = bias;
            #pragma unroll 8
            for (int kk = 0; kk < H; kk++) {
                float hlo, hhi;
                unpack2(*(const u64*)(sm + OFF_H2 + (eb[b] * 41 + kk) * 2), hlo, hhi);
                acc = fmaf(hlo, wfc[kk], acc);
            }
            out[ge[b] * 2 + j] = acc;
        }
    }
}

extern "C" void kernel_launch(void* const* d_in, const int* in_sizes, int n_in,
                              void* d_out, int out_size)
{
    const float* x     = (const float*)d_in[0];
    const float* W_ih1 = (const float*)d_in[1];
    const float* W_hh1 = (const float*)d_in[2];
    const float* b1    = (const float*)d_in[3];
    const float* W_ih2 = (const float*)d_in[4];
    const float* W_hh2 = (const float*)d_in[5];
    const float* b2    = (const float*)d_in[6];
    const float* W_fc  = (const float*)d_in[7];
    const float* b_fc  = (const float*)d_in[8];
    float* out = (float*)d_out;

    cudaFuncSetAttribute(lstm2_fused_kernel,
                         cudaFuncAttributeMaxDynamicSharedMemorySize, SMEM_BYTES);

    lstm2_fused_kernel<<<NBLOCKS, THREADS, SMEM_BYTES>>>(
        x, W_ih1, W_hh1, b1, W_ih2, W_hh2, b2, W_fc, b_fc, out);
}

// round 4
// speedup vs baseline: 1.0243x; 1.0243x over previous
#include <cuda_runtime.h>
#include <cuda_bf16.h>

#define H 40
#define T 256
#define BATCH 8192
#define EPB 32            // elements per block
#define THREADS 128       // 4 warps, 8 elements per warp, 2 per thread
#define NB 2              // batch elements per thread
#define NBLOCKS (BATCH / EPB)   // 256

typedef unsigned long long u64;

// ---- shared memory layout (float offsets) ----
#define OFF_WIH1 0                       // [k 40][c 3][g 4]      = 480
#define OFF_B1   480                     // [k 40][g 4]           = 160
#define OFF_B2   640                     // [k 40][g 4]           = 160
#define OFF_WHH1 800                     // [k 40][kk pitch41][g4]= 6560
#define OFF_WIH2 (800 + 6560)            // 7360
#define OFF_WHH2 (800 + 2*6560)          // 13920
#define OFF_H1   (800 + 3*6560)          // 20480 : [e 32][kk pitch41] x float2{h,h}
#define OFF_H2   (OFF_H1 + 2624)         // 23104
#define SMEM_FLOATS (OFF_H2 + 2624)      // 25728
#define SMEM_BYTES (SMEM_FLOATS * 4)     // 102912

__device__ __forceinline__ void fma2(u64 &d, u64 a, u64 b) {
    asm("fma.rn.f32x2 %0, %1, %2, %0;" : "+l"(d) : "l"(a), "l"(b));
}
__device__ __forceinline__ u64 pack2(float x, float y) {
    u64 r; asm("mov.b64 %0, {%1, %2};" : "=l"(r) : "f"(x), "f"(y)); return r;
}
__device__ __forceinline__ void unpack2(u64 v, float &x, float &y) {
    asm("mov.b64 {%0, %1}, %2;" : "=f"(x), "=f"(y) : "l"(v));
}
__device__ __forceinline__ float sigf(float x) {
    return __fdividef(1.0f, 1.0f + __expf(-x));
}
__device__ __forceinline__ float tanh_(float x) {
    float e = __expf(-2.0f * x);
    return __fdividef(1.0f - e, 1.0f + e);
}

__global__ __launch_bounds__(THREADS)
void lstm2_fused_kernel(const float* __restrict__ x,
                        const float* __restrict__ W_ih1,
                        const float* __restrict__ W_hh1,
                        const float* __restrict__ b1,
                        const float* __restrict__ W_ih2,
                        const float* __restrict__ W_hh2,
                        const float* __restrict__ b2,
                        const float* __restrict__ W_fc,
                        const float* __restrict__ b_fc,
                        float* __restrict__ out)
{
    extern __shared__ float sm[];
    const int tid = threadIdx.x;

    // ---- stage weights, gate-interleaved ----
    for (int idx = tid; idx < 160 * 3; idx += THREADS) {
        int row = idx / 3, c = idx % 3;
        int g = row / H, k = row % H;
        sm[OFF_WIH1 + (k * 3 + c) * 4 + g] = W_ih1[idx];
    }
    for (int idx = tid; idx < 160; idx += THREADS) {
        int g = idx / H, k = idx % H;
        sm[OFF_B1 + k * 4 + g] = b1[idx];
        sm[OFF_B2 + k * 4 + g] = b2[idx];
    }
    for (int idx = tid; idx < 160 * H; idx += THREADS) {
        int row = idx / H, kk = idx % H;
        int g = row / H, k = row % H;
        sm[OFF_WHH1 + (k * 41 + kk) * 4 + g] = W_hh1[idx];
        sm[OFF_WIH2 + (k * 41 + kk) * 4 + g] = W_ih2[idx];
        sm[OFF_WHH2 + (k * 41 + kk) * 4 + g] = W_hh2[idx];
    }
    for (int idx = tid; idx < 2 * 2624; idx += THREADS) {
        sm[OFF_H1 + idx] = 0.0f;   // covers H1 and H2 (contiguous)
    }
    __syncthreads();

    const int lane = tid & 31;
    const int warp = tid >> 5;
    const int j    = lane & 7;     // k-slice (owns k0..k0+4)
    const int sub  = lane >> 3;    // element subgroup within warp (0..3)
    const int k0   = j * 5;

    int eb[NB];                    // element index within block
    long ge[NB];                   // global element index
    const float* xb[NB];
    #pragma unroll
    for (int b = 0; b < NB; b++) {
        eb[b] = warp * 8 + sub * NB + b;
        ge[b] = (long)blockIdx.x * EPB + eb[b];
        xb[b] = x + ge[b] * (T * 3);
    }

    float c1[5][NB], c2[5][NB];
    #pragma unroll
    for (int k = 0; k < 5; k++)
        #pragma unroll
        for (int b = 0; b < NB; b++) { c1[k][b] = 0.0f; c2[k][b] = 0.0f; }

    // x for t=0
    float xv[NB][3];
    #pragma unroll
    for (int b = 0; b < NB; b++)
        #pragma unroll
        for (int c = 0; c < 3; c++)
            xv[b][c] = __ldg(xb[b] + c);

    for (int t = 0; t < T; t++) {
        // prefetch next x early
        float xn[NB][3];
        {
            int tn = (t + 1 < T) ? (t + 1) : (T - 1);
            #pragma unroll
            for (int b = 0; b < NB; b++)
                #pragma unroll
                for (int c = 0; c < 3; c++)
                    xn[b][c] = __ldg(xb[b] + tn * 3 + c);
        }

        // ================= layer 1 =================
        u64 aA[5][NB], aB[5][NB];   // aA = (i,f) packed, aB = (g,o) packed
        #pragma unroll
        for (int k = 0; k < 5; k++) {
            ulonglong2 bb = *(const ulonglong2*)(sm + OFF_B1 + (k0 + k) * 4);
            #pragma unroll
            for (int b = 0; b < NB; b++) { aA[k][b] = bb.x; aB[k][b] = bb.y; }
        }
        // input contribution
        #pragma unroll
        for (int c = 0; c < 3; c++) {
            u64 xp[NB];
            #pragma unroll
            for (int b = 0; b < NB; b++) xp[b] = pack2(xv[b][c], xv[b][c]);
            #pragma unroll
            for (int k = 0; k < 5; k++) {
                ulonglong2 w = *(const ulonglong2*)(sm + OFF_WIH1 + ((k0 + k) * 3 + c) * 4);
                #pragma unroll
                for (int b = 0; b < NB; b++) {
                    fma2(aA[k][b], w.x, xp[b]);
                    fma2(aB[k][b], w.y, xp[b]);
                }
            }
        }
        // recurrent contribution
        #pragma unroll 2
        for (int kk = 0; kk < H; kk++) {
            u64 hp[NB];
            #pragma unroll
            for (int b = 0; b < NB; b++)
                hp[b] = *(const u64*)(sm + OFF_H1 + (eb[b] * 41 + kk) * 2);
            #pragma unroll
            for (int k = 0; k < 5; k++) {
                ulonglong2 w = *(const ulonglong2*)(sm + OFF_WHH1 + ((k0 + k) * 41 + kk) * 4);
                #pragma unroll
                for (int b = 0; b < NB; b++) {
                    fma2(aA[k][b], w.x, hp[b]);
                    fma2(aB[k][b], w.y, hp[b]);
                }
            }
        }
        __syncwarp();   // all reads of old H1 done
        #pragma unroll
        for (int k = 0; k < 5; k++) {
            #pragma unroll
            for (int b = 0; b < NB; b++) {
                float gi, gf, gg, go;
                unpack2(aA[k][b], gi, gf);
                unpack2(aB[k][b], gg, go);
                gi = sigf(gi); gf = sigf(gf); gg = tanh_(gg); go = sigf(go);
                c1[k][b] = fmaf(gf, c1[k][b], gi * gg);
                float h = go * tanh_(c1[k][b]);
                *(u64*)(sm + OFF_H1 + (eb[b] * 41 + k0 + k) * 2) = pack2(h, h);
            }
        }
        __syncwarp();   // H1 new visible

        // ================= layer 2 (ih2 + hh2 fused) =================
        #pragma unroll
        for (int k = 0; k < 5; k++) {
            ulonglong2 bb = *(const ulonglong2*)(sm + OFF_B2 + (k0 + k) * 4);
            #pragma unroll
            for (int b = 0; b < NB; b++) { aA[k][b] = bb.x; aB[k][b] = bb.y; }
        }
        #pragma unroll 2
        for (int kk = 0; kk < H; kk++) {
            u64 h1p[NB], h2p[NB];
            #pragma unroll
            for (int b = 0; b < NB; b++) {
                h1p[b] = *(const u64*)(sm + OFF_H1 + (eb[b] * 41 + kk) * 2);
                h2p[b] = *(const u64*)(sm + OFF_H2 + (eb[b] * 41 + kk) * 2);
            }
            #pragma unroll
            for (int k = 0; k < 5; k++) {
                ulonglong2 w1 = *(const ulonglong2*)(sm + OFF_WIH2 + ((k0 + k) * 41 + kk) * 4);
                ulonglong2 w2 = *(const ulonglong2*)(sm + OFF_WHH2 + ((k0 + k) * 41 + kk) * 4);
                #pragma unroll
                for (int b = 0; b < NB; b++) {
                    fma2(aA[k][b], w1.x, h1p[b]);
                    fma2(aB[k][b], w1.y, h1p[b]);
                    fma2(aA[k][b], w2.x, h2p[b]);
                    fma2(aB[k][b], w2.y, h2p[b]);
                }
            }
        }
        __syncwarp();   // all reads of old H2 done
        #pragma unroll
        for (int k = 0; k < 5; k++) {
            #pragma unroll
            for (int b = 0; b < NB; b++) {
                float gi, gf, gg, go;
                unpack2(aA[k][b], gi, gf);
                unpack2(aB[k][b], gg, go);
                gi = sigf(gi); gf = sigf(gf); gg = tanh_(gg); go = sigf(go);
                c2[k][b] = fmaf(gf, c2[k][b], gi * gg);
                float h = go * tanh_(c2[k][b]);
                *(u64*)(sm + OFF_H2 + (eb[b] * 41 + k0 + k) * 2) = pack2(h, h);
            }
        }
        __syncwarp();   // H2 new visible

        #pragma unroll
        for (int b = 0; b < NB; b++) {
            xv[b][0] = xn[b][0]; xv[b][1] = xn[b][1]; xv[b][2] = xn[b][2];
        }
    }

    // ================= FC epilogue =================
    if (j < 2) {
        float wfc[H];
        #pragma unroll 8
        for (int kk = 0; kk < H; kk++) wfc[kk] = W_fc[j * H + kk];
        float bias = b_fc[j];
        #pragma unroll
        for (int b = 0; b < NB; b++) {
            float acc = bias;
            #pragma unroll 8
            for (int kk = 0; kk < H; kk++) {
                float hlo, hhi;
                unpack2(*(const u64*)(sm + OFF_H2 + (eb[b] * 41 + kk) * 2), hlo, hhi);
                acc = fmaf(hlo, wfc[kk], acc);
            }
            out[ge[b] * 2 + j] = acc;
        }
    }
}

extern "C" void kernel_launch(void* const* d_in, const int* in_sizes, int n_in,
                              void* d_out, int out_size)
{
    const float* x     = (const float*)d_in[0];
    const float* W_ih1 = (const float*)d_in[1];
    const float* W_hh1 = (const float*)d_in[2];
    const float* b1    = (const float*)d_in[3];
    const float* W_ih2 = (const float*)d_in[4];
    const float* W_hh2 = (const float*)d_in[5];
    const float* b2    = (const float*)d_in[6];
    const float* W_fc  = (const float*)d_in[7];
    const float* b_fc  = (const float*)d_in[8];
    float* out = (float*)d_out;

    cudaFuncSetAttribute(lstm2_fused_kernel,
                         cudaFuncAttributeMaxDynamicSharedMemorySize, SMEM_BYTES);

    lstm2_fused_kernel<<<NBLOCKS, THREADS, SMEM_BYTES>>>(
        x, W_ih1, W_hh1, b1, W_ih2, W_hh2, b2, W_fc, b_fc, out);
}

// round 6
// speedup vs baseline: 1.6503x; 1.6112x over previous
#include <cuda_runtime.h>
#include <cuda_bf16.h>

#define H 40
#define T 256
#define BATCH 8192
#define EPB 32            // elements per block
#define THREADS 64        // 2 warps, 16 elements per warp, 4 per thread
#define NB 4
#define NBLOCKS (BATCH / EPB)   // 256

typedef unsigned long long u64;

// ---- shared memory layout (float offsets) ----
#define OFF_WIH1 0                       // [k 40][c 3][g 4]      = 480
#define OFF_B1   480                     // [k 40][g 4]           = 160
#define OFF_B2   640                     // [k 40][g 4]           = 160
#define OFF_WHH1 800                     // [k 40][kk pitch41][g4]= 6560
#define OFF_WIH2 (800 + 6560)            // 7360
#define OFF_WHH2 (800 + 2*6560)          // 13920
#define OFF_HC   (800 + 3*6560)          // 20480 : [e 32][kk pitch41] float4 {h1,h1,h2,h2}
#define HC_ESTRIDE 164                   // 41 float4 = 164 floats (odd float4 stride)
#define SMEM_FLOATS (OFF_HC + EPB * HC_ESTRIDE)   // 25728
#define SMEM_BYTES (SMEM_FLOATS * 4)     // 102912

__device__ __forceinline__ void fma2(u64 &d, u64 a, u64 b) {
    asm("fma.rn.f32x2 %0, %1, %2, %0;" : "+l"(d) : "l"(a), "l"(b));
}
__device__ __forceinline__ u64 pack2(float x, float y) {
    u64 r; asm("mov.b64 %0, {%1, %2};" : "=l"(r) : "f"(x), "f"(y)); return r;
}
__device__ __forceinline__ void unpack2(u64 v, float &x, float &y) {
    asm("mov.b64 {%0, %1}, %2;" : "=f"(x), "=f"(y) : "l"(v));
}
__device__ __forceinline__ float tanhfast(float x) {
    float y; asm("tanh.approx.f32 %0, %1;" : "=f"(y) : "f"(x)); return y;
}
__device__ __forceinline__ float sigf(float x) {
    return fmaf(0.5f, tanhfast(0.5f * x), 0.5f);
}

__global__ __launch_bounds__(THREADS)
void lstm2_fused_kernel(const float* __restrict__ x,
                        const float* __restrict__ W_ih1,
                        const float* __restrict__ W_hh1,
                        const float* __restrict__ b1,
                        const float* __restrict__ W_ih2,
                        const float* __restrict__ W_hh2,
                        const float* __restrict__ b2,
                        const float* __restrict__ W_fc,
                        const float* __restrict__ b_fc,
                        float* __restrict__ out)
{
    extern __shared__ float sm[];
    const int tid = threadIdx.x;

    // ---- stage weights, gate-interleaved ----
    for (int idx = tid; idx < 160 * 3; idx += THREADS) {
        int row = idx / 3, c = idx % 3;
        int g = row / H, k = row % H;
        sm[OFF_WIH1 + (k * 3 + c) * 4 + g] = W_ih1[idx];
    }
    for (int idx = tid; idx < 160; idx += THREADS) {
        int g = idx / H, k = idx % H;
        sm[OFF_B1 + k * 4 + g] = b1[idx];
        sm[OFF_B2 + k * 4 + g] = b2[idx];
    }
    for (int idx = tid; idx < 160 * H; idx += THREADS) {
        int row = idx / H, kk = idx % H;
        int g = row / H, k = row % H;
        sm[OFF_WHH1 + (k * 41 + kk) * 4 + g] = W_hh1[idx];
        sm[OFF_WIH2 + (k * 41 + kk) * 4 + g] = W_ih2[idx];
        sm[OFF_WHH2 + (k * 41 + kk) * 4 + g] = W_hh2[idx];
    }
    for (int idx = tid; idx < EPB * HC_ESTRIDE; idx += THREADS) {
        sm[OFF_HC + idx] = 0.0f;
    }
    __syncthreads();

    const int lane = tid & 31;
    const int warp = tid >> 5;
    const int j    = lane & 7;     // k-slice (owns k0..k0+4)
    const int sub  = lane >> 3;    // 0..3
    const int k0   = j * 5;

    int eb[NB];
    long ge[NB];
    const float* xb[NB];
    #pragma unroll
    for (int b = 0; b < NB; b++) {
        eb[b] = warp * 16 + b * 4 + sub;   // sub-consecutive: conflict-free h reads
        ge[b] = (long)blockIdx.x * EPB + eb[b];
        xb[b] = x + ge[b] * (T * 3);
    }

    float c1[5][NB], c2[5][NB];
    #pragma unroll
    for (int k = 0; k < 5; k++)
        #pragma unroll
        for (int b = 0; b < NB; b++) { c1[k][b] = 0.0f; c2[k][b] = 0.0f; }

    // x for t=0
    float xv[NB][3];
    #pragma unroll
    for (int b = 0; b < NB; b++)
        #pragma unroll
        for (int c = 0; c < 3; c++)
            xv[b][c] = __ldg(xb[b] + c);

    float* __restrict__ HC = sm + OFF_HC;

    for (int t = 0; t < T; t++) {
        // prefetch next x early
        float xn[NB][3];
        {
            int tn = (t + 1 < T) ? (t + 1) : (T - 1);
            #pragma unroll
            for (int b = 0; b < NB; b++)
                #pragma unroll
                for (int c = 0; c < 3; c++)
                    xn[b][c] = __ldg(xb[b] + tn * 3 + c);
        }

        // ================= layer 1 =================
        u64 aA[5][NB], aB[5][NB];   // aA = (i,f), aB = (g,o)
        #pragma unroll
        for (int k = 0; k < 5; k++) {
            ulonglong2 bb = *(const ulonglong2*)(sm + OFF_B1 + (k0 + k) * 4);
            #pragma unroll
            for (int b = 0; b < NB; b++) { aA[k][b] = bb.x; aB[k][b] = bb.y; }
        }
        #pragma unroll
        for (int c = 0; c < 3; c++) {
            u64 xp[NB];
            #pragma unroll
            for (int b = 0; b < NB; b++) xp[b] = pack2(xv[b][c], xv[b][c]);
            #pragma unroll
            for (int k = 0; k < 5; k++) {
                ulonglong2 w = *(const ulonglong2*)(sm + OFF_WIH1 + ((k0 + k) * 3 + c) * 4);
                #pragma unroll
                for (int b = 0; b < NB; b++) {
                    fma2(aA[k][b], w.x, xp[b]);
                    fma2(aB[k][b], w.y, xp[b]);
                }
            }
        }
        // recurrent: read h1 pairs {h1,h1} from interleaved HC (lower half of float4)
        #pragma unroll 5
        for (int kk = 0; kk < H; kk++) {
            u64 hp[NB];
            #pragma unroll
            for (int b = 0; b < NB; b++)
                hp[b] = *(const u64*)(HC + eb[b] * HC_ESTRIDE + kk * 4);
            #pragma unroll
            for (int k = 0; k < 5; k++) {
                ulonglong2 w = *(const ulonglong2*)(sm + OFF_WHH1 + ((k0 + k) * 41 + kk) * 4);
                #pragma unroll
                for (int b = 0; b < NB; b++) {
                    fma2(aA[k][b], w.x, hp[b]);
                    fma2(aB[k][b], w.y, hp[b]);
                }
            }
        }
        __syncwarp();   // all reads of old h1 done
        #pragma unroll
        for (int k = 0; k < 5; k++) {
            #pragma unroll
            for (int b = 0; b < NB; b++) {
                float gi, gf, gg, go;
                unpack2(aA[k][b], gi, gf);
                unpack2(aB[k][b], gg, go);
                gi = sigf(gi); gf = sigf(gf); gg = tanhfast(gg); go = sigf(go);
                c1[k][b] = fmaf(gf, c1[k][b], gi * gg);
                float h = go * tanhfast(c1[k][b]);
                *(u64*)(HC + eb[b] * HC_ESTRIDE + (k0 + k) * 4) = pack2(h, h);
            }
        }
        __syncwarp();   // h1(t) visible

        // ================= layer 2 (ih2 + hh2 fused) =================
        #pragma unroll
        for (int k = 0; k < 5; k++) {
            ulonglong2 bb = *(const ulonglong2*)(sm + OFF_B2 + (k0 + k) * 4);
            #pragma unroll
            for (int b = 0; b < NB; b++) { aA[k][b] = bb.x; aB[k][b] = bb.y; }
        }
        #pragma unroll 5
        for (int kk = 0; kk < H; kk++) {
            ulonglong2 hq[NB];   // .x = {h1,h1}, .y = {h2,h2}
            #pragma unroll
            for (int b = 0; b < NB; b++)
                hq[b] = *(const ulonglong2*)(HC + eb[b] * HC_ESTRIDE + kk * 4);
            #pragma unroll
            for (int k = 0; k < 5; k++) {
                ulonglong2 w1 = *(const ulonglong2*)(sm + OFF_WIH2 + ((k0 + k) * 41 + kk) * 4);
                ulonglong2 w2 = *(const ulonglong2*)(sm + OFF_WHH2 + ((k0 + k) * 41 + kk) * 4);
                #pragma unroll
                for (int b = 0; b < NB; b++) {
                    fma2(aA[k][b], w1.x, hq[b].x);
                    fma2(aB[k][b], w1.y, hq[b].x);
                    fma2(aA[k][b], w2.x, hq[b].y);
                    fma2(aB[k][b], w2.y, hq[b].y);
                }
            }
        }
        __syncwarp();   // all reads of old h2 done
        #pragma unroll
        for (int k = 0; k < 5; k++) {
            #pragma unroll
            for (int b = 0; b < NB; b++) {
                float gi, gf, gg, go;
                unpack2(aA[k][b], gi, gf);
                unpack2(aB[k][b], gg, go);
                gi = sigf(gi); gf = sigf(gf); gg = tanhfast(gg); go = sigf(go);
                c2[k][b] = fmaf(gf, c2[k][b], gi * gg);
                float h = go * tanhfast(c2[k][b]);
                *(u64*)(HC + eb[b] * HC_ESTRIDE + (k0 + k) * 4 + 2) = pack2(h, h);
            }
        }
        // no syncwarp needed here: next read of h2 is after two syncwarps (next step's L2)

        #pragma unroll
        for (int b = 0; b < NB; b++) {
            xv[b][0] = xn[b][0]; xv[b][1] = xn[b][1]; xv[b][2] = xn[b][2];
        }
    }
    __syncwarp();

    // ================= FC epilogue =================
    if (j < 2) {
        float wfc[H];
        #pragma unroll 8
        for (int kk = 0; kk < H; kk++) wfc[kk] = W_fc[j * H + kk];
        float bias = b_fc[j];
        #pragma unroll
        for (int b = 0; b < NB; b++) {
            float acc = bias;
            #pragma unroll 8
            for (int kk = 0; kk < H; kk++) {
                float hlo, hhi;
                unpack2(*(const u64*)(HC + eb[b] * HC_ESTRIDE + kk * 4 + 2), hlo, hhi);
                acc = fmaf(hlo, wfc[kk], acc);
            }
            out[ge[b] * 2 + j] = acc;
        }
    }
}

extern "C" void kernel_launch(void* const* d_in, const int* in_sizes, int n_in,
                              void* d_out, int out_size)
{
    const float* x     = (const float*)d_in[0];
    const float* W_ih1 = (const float*)d_in[1];
    const float* W_hh1 = (const float*)d_in[2];
    const float* b1    = (const float*)d_in[3];
    const float* W_ih2 = (const float*)d_in[4];
    const float* W_hh2 = (const float*)d_in[5];
    const float* b2    = (const float*)d_in[6];
    const float* W_fc  = (const float*)d_in[7];
    const float* b_fc  = (const float*)d_in[8];
    float* out = (float*)d_out;

    cudaFuncSetAttribute(lstm2_fused_kernel,
                         cudaFuncAttributeMaxDynamicSharedMemorySize, SMEM_BYTES);

    lstm2_fused_kernel<<<NBLOCKS, THREADS, SMEM_BYTES>>>(
        x, W_ih1, W_hh1, b1, W_ih2, W_hh2, b2, W_fc, b_fc, out);
}